// round 1
// baseline (speedup 1.0000x reference)
#include <cuda_runtime.h>
#include <cuda_bf16.h>
#include <math.h>

#define N_TOK 2048
#define HDIM  256
#define NHEAD 8
#define DHEAD 32
#define FFDIM 512
#define NLAYER 6
#define CAP   96

// -------- device scratch (no allocations allowed) --------
__device__ float g_X  [N_TOK * HDIM];
__device__ float g_Hn [N_TOK * HDIM];
__device__ float g_QKV[N_TOK * 3 * HDIM];
__device__ float g_ATT[N_TOK * HDIM];
__device__ float g_FF [N_TOK * FFDIM];
__device__ float g_T1 [N_TOK * HDIM];
__device__ float g_T2 [N_TOK * (HDIM/2)];
__device__ float g_eta[N_TOK];
__device__ float g_phi[N_TOK];
__device__ int   g_nbr[N_TOK * CAP];
__device__ int   g_cnt[N_TOK];

// -------- embed: x = x_raw @ Win^T + b_in ; also eta/phi --------
__global__ void embed_kernel(const float* __restrict__ xr,
                             const float* __restrict__ Win,
                             const float* __restrict__ b_in) {
    int n = blockIdx.x;
    int h = threadIdx.x;               // 256
    __shared__ float r[8];
    if (h < 8) r[h] = xr[n * 8 + h];
    __syncthreads();
    float acc = b_in[h];
#pragma unroll
    for (int k = 0; k < 8; k++) acc += r[k] * Win[h * 8 + k];
    g_X[n * HDIM + h] = acc;
    if (h == 0) {
        g_eta[n] = r[1] * 5.24f   - 2.62f;
        g_phi[n] = r[2] * 6.2832f - 3.1416f;
    }
}

// -------- neighbor list build (deterministic, ordered) --------
__global__ void build_nbr_kernel() {
    int warp = (blockIdx.x * blockDim.x + threadIdx.x) >> 5;
    int lane = threadIdx.x & 31;
    if (warp >= N_TOK) return;
    int i = warp;
    float ei = g_eta[i], pi = g_phi[i];
    int c = 0;
    for (int j0 = 0; j0 < N_TOK; j0 += 32) {
        int j = j0 + lane;
        float de = ei - g_eta[j];
        float dp = pi - g_phi[j];
        // wrap to (-pi, pi]
        dp = dp - 6.283185307179586f * rintf(dp * 0.15915494309189535f);
        float dr2 = de * de + dp * dp;
        bool keep = (dr2 <= 0.04f);
        unsigned m = __ballot_sync(0xffffffffu, keep);
        if (keep) {
            int pos = c + __popc(m & ((1u << lane) - 1u));
            if (pos < CAP) g_nbr[i * CAP + pos] = j;
        }
        c += __popc(m);
    }
    if (lane == 0) g_cnt[i] = (c < CAP) ? c : CAP;
}

// -------- LayerNorm over H=256 (one block per row) --------
__global__ void ln_kernel(const float* __restrict__ x,
                          const float* __restrict__ g,
                          const float* __restrict__ b,
                          float* __restrict__ out) {
    int n = blockIdx.x;
    int t = threadIdx.x;               // 256
    __shared__ float r1[8], r2[8];
    float v = x[n * HDIM + t];
    float s = v;
#pragma unroll
    for (int off = 16; off; off >>= 1) s += __shfl_xor_sync(0xffffffffu, s, off);
    if ((t & 31) == 0) r1[t >> 5] = s;
    __syncthreads();
    float tot = 0.f;
#pragma unroll
    for (int w = 0; w < 8; w++) tot += r1[w];
    float mean = tot * (1.f / 256.f);
    float d = v - mean;
    float s2 = d * d;
#pragma unroll
    for (int off = 16; off; off >>= 1) s2 += __shfl_xor_sync(0xffffffffu, s2, off);
    if ((t & 31) == 0) r2[t >> 5] = s2;
    __syncthreads();
    float vtot = 0.f;
#pragma unroll
    for (int w = 0; w < 8; w++) vtot += r2[w];
    float var = vtot * (1.f / 256.f);
    out[n * HDIM + t] = d * rsqrtf(var + 1e-5f) * g[t] + b[t];
}

// -------- generic tiled SGEMM: C[M,N] = A[M,K] @ B[N,K]^T + bias (+relu)(+resid) --------
template<bool RELU, bool RES>
__global__ void gemm_kernel(const float* __restrict__ A, const float* __restrict__ B,
                            const float* __restrict__ bias, const float* __restrict__ R,
                            float* __restrict__ C, int M, int Ncols, int K) {
    __shared__ __align__(16) float As[16][68];
    __shared__ __align__(16) float Bs[16][68];
    int tx = threadIdx.x, ty = threadIdx.y;            // 16 x 16
    int tid = ty * 16 + tx;
    int m0 = blockIdx.y * 64, n0 = blockIdx.x * 64;
    int lr = tid >> 2;                                  // row within tile 0..63
    int lc = (tid & 3) * 4;                             // k chunk 0,4,8,12

    float acc[4][4];
#pragma unroll
    for (int i = 0; i < 4; i++)
#pragma unroll
        for (int j = 0; j < 4; j++) acc[i][j] = 0.f;

    const float* Ag = A + (size_t)(m0 + lr) * K + lc;
    bool bvalid = (n0 + lr) < Ncols;
    const float* Bg = B + (size_t)(n0 + lr) * K + lc;

    for (int k0 = 0; k0 < K; k0 += 16) {
        float4 av = *(const float4*)(Ag + k0);
        float4 bv = bvalid ? *(const float4*)(Bg + k0) : make_float4(0.f, 0.f, 0.f, 0.f);
        As[lc + 0][lr] = av.x; As[lc + 1][lr] = av.y;
        As[lc + 2][lr] = av.z; As[lc + 3][lr] = av.w;
        Bs[lc + 0][lr] = bv.x; Bs[lc + 1][lr] = bv.y;
        Bs[lc + 2][lr] = bv.z; Bs[lc + 3][lr] = bv.w;
        __syncthreads();
#pragma unroll
        for (int kk = 0; kk < 16; kk++) {
            float4 a = *(const float4*)&As[kk][ty * 4];
            float4 b = *(const float4*)&Bs[kk][tx * 4];
            acc[0][0] += a.x * b.x; acc[0][1] += a.x * b.y; acc[0][2] += a.x * b.z; acc[0][3] += a.x * b.w;
            acc[1][0] += a.y * b.x; acc[1][1] += a.y * b.y; acc[1][2] += a.y * b.z; acc[1][3] += a.y * b.w;
            acc[2][0] += a.z * b.x; acc[2][1] += a.z * b.y; acc[2][2] += a.z * b.z; acc[2][3] += a.z * b.w;
            acc[3][0] += a.w * b.x; acc[3][1] += a.w * b.y; acc[3][2] += a.w * b.z; acc[3][3] += a.w * b.w;
        }
        __syncthreads();
    }

#pragma unroll
    for (int i = 0; i < 4; i++) {
        int row = m0 + ty * 4 + i;
#pragma unroll
        for (int j = 0; j < 4; j++) {
            int col = n0 + tx * 4 + j;
            if (col < Ncols) {
                float v = acc[i][j] + bias[col];
                if (RELU) v = fmaxf(v, 0.f);
                if (RES)  v += R[(size_t)row * Ncols + col];
                C[(size_t)row * Ncols + col] = v;
            }
        }
    }
}

// -------- sparse attention: one warp per (query, head) --------
__global__ void attn_kernel() {
    int warp = (blockIdx.x * blockDim.x + threadIdx.x) >> 5;
    int lane = threadIdx.x & 31;
    int n = warp >> 3;
    int h = warp & 7;
    if (n >= N_TOK) return;
    const float scale = 0.17677669529663687f;   // 1/sqrt(32)
    float q = g_QKV[n * 768 + h * 32 + lane];
    int c = g_cnt[n];
    float m = -1e30f, s = 0.f, o = 0.f;
    for (int t = 0; t < c; t++) {
        int j = g_nbr[n * CAP + t];
        float kv = g_QKV[j * 768 + 256 + h * 32 + lane];
        float prod = q * kv;
#pragma unroll
        for (int off = 16; off; off >>= 1) prod += __shfl_xor_sync(0xffffffffu, prod, off);
        float sc = prod * scale;
        float mn = fmaxf(m, sc);
        float corr = __expf(m - mn);
        float p = __expf(sc - mn);
        s = s * corr + p;
        float v = g_QKV[j * 768 + 512 + h * 32 + lane];
        o = o * corr + p * v;
        m = mn;
    }
    g_ATT[n * 256 + h * 32 + lane] = o / s;
}

// -------- beta head: zb = T2 @ Wb2^T + bb2 ; beta = clip(sigmoid(zb)) --------
__global__ void beta_kernel(const float* __restrict__ Wb2,
                            const float* __restrict__ bb2,
                            float* __restrict__ out) {
    int warp = (blockIdx.x * blockDim.x + threadIdx.x) >> 5;
    int lane = threadIdx.x & 31;
    if (warp >= N_TOK) return;
    float s = 0.f;
#pragma unroll
    for (int k = lane; k < 128; k += 32) s += g_T2[warp * 128 + k] * Wb2[k];
#pragma unroll
    for (int off = 16; off; off >>= 1) s += __shfl_xor_sync(0xffffffffu, s, off);
    if (lane == 0) {
        float z = s + bb2[0];
        float b = 1.f / (1.f + expf(-z));
        b = fminf(fmaxf(b, 1e-6f), 1.f - 1e-6f);
        out[warp] = b;
    }
}

extern "C" void kernel_launch(void* const* d_in, const int* in_sizes, int n_in,
                              void* d_out, int out_size) {
    const float* x_raw = (const float*)d_in[0];
    // d_in[1] = batch (unused)
    const float* Win  = (const float*)d_in[2];
    const float* b_in = (const float*)d_in[3];
    const float* Wqkv = (const float*)d_in[4];
    const float* bqkv = (const float*)d_in[5];
    const float* Wo   = (const float*)d_in[6];
    const float* bo   = (const float*)d_in[7];
    const float* W1   = (const float*)d_in[8];
    const float* b1   = (const float*)d_in[9];
    const float* W2   = (const float*)d_in[10];
    const float* b2   = (const float*)d_in[11];
    const float* g1   = (const float*)d_in[12];
    const float* be1  = (const float*)d_in[13];
    const float* g2   = (const float*)d_in[14];
    const float* be2  = (const float*)d_in[15];
    const float* Wl1  = (const float*)d_in[16];
    const float* bl1  = (const float*)d_in[17];
    const float* Wl2  = (const float*)d_in[18];
    const float* bl2  = (const float*)d_in[19];
    const float* Wb1  = (const float*)d_in[20];
    const float* bb1  = (const float*)d_in[21];
    const float* Wb2  = (const float*)d_in[22];
    const float* bb2  = (const float*)d_in[23];
    float* out = (float*)d_out;

    float *pX, *pH, *pQKV, *pATT, *pFF, *pT1, *pT2;
    cudaGetSymbolAddress((void**)&pX,   g_X);
    cudaGetSymbolAddress((void**)&pH,   g_Hn);
    cudaGetSymbolAddress((void**)&pQKV, g_QKV);
    cudaGetSymbolAddress((void**)&pATT, g_ATT);
    cudaGetSymbolAddress((void**)&pFF,  g_FF);
    cudaGetSymbolAddress((void**)&pT1,  g_T1);
    cudaGetSymbolAddress((void**)&pT2,  g_T2);

    dim3 tb(16, 16);

    embed_kernel<<<N_TOK, HDIM>>>(x_raw, Win, b_in);
    build_nbr_kernel<<<N_TOK / 8, 256>>>();

    for (int l = 0; l < NLAYER; l++) {
        const float* Wqkv_l = Wqkv + (size_t)l * 3 * HDIM * HDIM;
        const float* bqkv_l = bqkv + (size_t)l * 3 * HDIM;
        const float* Wo_l   = Wo   + (size_t)l * HDIM * HDIM;
        const float* bo_l   = bo   + (size_t)l * HDIM;
        const float* W1_l   = W1   + (size_t)l * FFDIM * HDIM;
        const float* b1_l   = b1   + (size_t)l * FFDIM;
        const float* W2_l   = W2   + (size_t)l * HDIM * FFDIM;
        const float* b2_l   = b2   + (size_t)l * HDIM;

        ln_kernel<<<N_TOK, HDIM>>>(pX, g1 + l * HDIM, be1 + l * HDIM, pH);
        gemm_kernel<false, false><<<dim3(768 / 64, N_TOK / 64), tb>>>(
            pH, Wqkv_l, bqkv_l, nullptr, pQKV, N_TOK, 768, HDIM);
        attn_kernel<<<(N_TOK * NHEAD * 32) / 256, 256>>>();
        gemm_kernel<false, true><<<dim3(HDIM / 64, N_TOK / 64), tb>>>(
            pATT, Wo_l, bo_l, pX, pX, N_TOK, HDIM, HDIM);
        ln_kernel<<<N_TOK, HDIM>>>(pX, g2 + l * HDIM, be2 + l * HDIM, pH);
        gemm_kernel<true, false><<<dim3(FFDIM / 64, N_TOK / 64), tb>>>(
            pH, W1_l, b1_l, nullptr, pFF, N_TOK, FFDIM, HDIM);
        gemm_kernel<false, true><<<dim3(HDIM / 64, N_TOK / 64), tb>>>(
            pFF, W2_l, b2_l, pX, pX, N_TOK, HDIM, FFDIM);
    }

    // coords head: out[2048 .. 2048+49152) as [N, 24] row-major
    gemm_kernel<true, false><<<dim3(HDIM / 64, N_TOK / 64), tb>>>(
        pX, Wl1, bl1, nullptr, pT1, N_TOK, HDIM, HDIM);
    gemm_kernel<false, false><<<dim3(1, N_TOK / 64), tb>>>(
        pT1, Wl2, bl2, nullptr, out + N_TOK, N_TOK, 24, HDIM);

    // beta head: out[0 .. 2048)
    gemm_kernel<true, false><<<dim3(128 / 64, N_TOK / 64), tb>>>(
        pX, Wb1, bb1, nullptr, pT2, N_TOK, 128, HDIM);
    beta_kernel<<<(N_TOK * 32) / 256, 256>>>(Wb2, bb2, out);
}